// round 13
// baseline (speedup 1.0000x reference)
#include <cuda_runtime.h>
#include <math.h>

#define BB 64
#define SS 512
#define FF 128
#define UU 512
#define SIGDIM (FF + FF*FF)   /* 16512 */
#define NBF 8
#define TT (SS-1)             /* 511 */
#define BU (BB*UU)            /* 32768 */
#define KSTEP 16

typedef unsigned long long ull;

/* ---------------- packed f32x2 / tf32 helpers ---------------- */
__device__ __forceinline__ ull fma2(ull a, ull b, ull c)
{
    ull d;
    asm("fma.rn.f32x2 %0, %1, %2, %3;" : "=l"(d) : "l"(a), "l"(b), "l"(c));
    return d;
}
__device__ __forceinline__ float2 unpack2(ull v)
{
    float2 f;
    asm("mov.b64 {%0,%1}, %2;" : "=f"(f.x), "=f"(f.y) : "l"(v));
    return f;
}
__device__ __forceinline__ ull pack2(float x, float y)
{
    ull r;
    asm("mov.b64 %0, {%1,%2};" : "=l"(r) : "f"(x), "f"(y));
    return r;
}
__device__ __forceinline__ float tf32r(float x)
{
    unsigned r;
    asm("cvt.rna.tf32.f32 %0, %1;" : "=r"(r) : "f"(x));
    return __uint_as_float(r);
}
__device__ __forceinline__ unsigned tf32b(float x)
{
    unsigned r;
    asm("cvt.rna.tf32.f32 %0, %1;" : "=r"(r) : "f"(x));
    return r;
}

/* ---------------- scratch (no allocations allowed) ---------------- */
__device__ float g_sig[BB*SIGDIM];    /* stored pre-rounded to tf32 */
__device__ float g_z1[BU];
__device__ float g_zs[BU];
__device__ float g_attn[BU];
__device__ float g_Ab[BB*FF];
__device__ float g_As[BB*FF*NBF];
__device__ float g_cur[BU];
__device__ float g_gates[4*BU];

/* ---------------- zero the atomic accumulators ---------------- */
__global__ void k_zero()
{
    int i = blockIdx.x * blockDim.x + threadIdx.x;
    int n = blockDim.x * gridDim.x;
    for (int j = i; j < BU; j += n) {
        g_z1[j] = 0.f; g_zs[j] = 0.f; g_cur[j] = 0.f;
        g_gates[j] = 0.f; g_gates[BU + j] = 0.f;
        g_gates[2*BU + j] = 0.f; g_gates[3*BU + j] = 0.f;
    }
    for (int j = i; j < BB*FF*NBF; j += n) {
        g_As[j] = 0.f;
        if (j < BB*FF) g_Ab[j] = 0.f;
    }
}

/* =================================================================
   k_sig: s1 + s2 via tf32 mma.sync.
   P[t,i] = 0.5*(w[t,i]+w[t+1,i]) - w[0,i]; D[t,j] = w[t+1,j]-w[t,j]
   s2[i,j] = sum_t P[t,i]*D[t,j].
   grid (2 i-tiles, 64 batches), 256 threads = 8 warps.
   warp: row-group (warp>>1)*16, col-half (warp&1)*64 -> 8 n-frags.
   As[t][i] pad 72, Bs[t][j] pad 136: fragment LDS conflict-free.
   ================================================================= */
__global__ void __launch_bounds__(256)
k_sig(const float* __restrict__ X, const float* __restrict__ tk)
{
    int i0 = blockIdx.x * 64;
    int b  = blockIdx.y;
    int tid = threadIdx.x;
    int lane = tid & 31, warp = tid >> 5;
    int g = lane >> 2, t4 = lane & 3;
    int m0w = (warp >> 1) * 16;
    int jb  = (warp & 1) * 64;
    const float* Xb = X + (size_t)b * SS * FF;
    float tk0 = __ldg(&tk[0]);

    __shared__ __align__(16) unsigned As[32*72];
    __shared__ __align__(16) unsigned Bs[32*136];
    __shared__ float w0sh[64];

    if (tid < 64) w0sh[tid] = tk0 * __ldg(&Xb[i0 + tid]);

    float c[8][4];
    #pragma unroll
    for (int j = 0; j < 8; j++)
        { c[j][0]=0.f; c[j][1]=0.f; c[j][2]=0.f; c[j][3]=0.f; }

    int tt = tid >> 3;          /* 0..31 : t within chunk   */
    int i8 = (tid & 7) * 8;     /* P staging: 8 i values    */
    int j16 = (tid & 7) * 16;   /* D staging: 16 j values   */

    for (int t0 = 0; t0 < TT; t0 += 32) {
        __syncthreads();
        int t = t0 + tt;
        bool v = t < TT;
        float tkt = 0.f, tkt1 = 0.f;
        if (v) { tkt = __ldg(&tk[t]); tkt1 = __ldg(&tk[t+1]); }
        /* ---- P staging ---- */
        {
            unsigned* ap = &As[tt*72 + i8];
            if (v) {
                float4 x0 = *reinterpret_cast<const float4*>(&Xb[(size_t)t*FF + i0 + i8]);
                float4 x1 = *reinterpret_cast<const float4*>(&Xb[(size_t)t*FF + i0 + i8 + 4]);
                float4 y0 = *reinterpret_cast<const float4*>(&Xb[(size_t)(t+1)*FF + i0 + i8]);
                float4 y1 = *reinterpret_cast<const float4*>(&Xb[(size_t)(t+1)*FF + i0 + i8 + 4]);
                ap[0] = tf32b(0.5f*(tkt*x0.x + tkt1*y0.x) - w0sh[i8+0]);
                ap[1] = tf32b(0.5f*(tkt*x0.y + tkt1*y0.y) - w0sh[i8+1]);
                ap[2] = tf32b(0.5f*(tkt*x0.z + tkt1*y0.z) - w0sh[i8+2]);
                ap[3] = tf32b(0.5f*(tkt*x0.w + tkt1*y0.w) - w0sh[i8+3]);
                ap[4] = tf32b(0.5f*(tkt*x1.x + tkt1*y1.x) - w0sh[i8+4]);
                ap[5] = tf32b(0.5f*(tkt*x1.y + tkt1*y1.y) - w0sh[i8+5]);
                ap[6] = tf32b(0.5f*(tkt*x1.z + tkt1*y1.z) - w0sh[i8+6]);
                ap[7] = tf32b(0.5f*(tkt*x1.w + tkt1*y1.w) - w0sh[i8+7]);
            } else {
                #pragma unroll
                for (int q = 0; q < 8; q++) ap[q] = 0u;
            }
        }
        /* ---- D staging ---- */
        {
            unsigned* bp = &Bs[tt*136 + j16];
            if (v) {
                const float* xr = &Xb[(size_t)t*FF + j16];
                const float* yr = &Xb[(size_t)(t+1)*FF + j16];
                #pragma unroll
                for (int q = 0; q < 4; q++) {
                    float4 xv = *reinterpret_cast<const float4*>(xr + 4*q);
                    float4 yv = *reinterpret_cast<const float4*>(yr + 4*q);
                    bp[4*q+0] = tf32b(tkt1*yv.x - tkt*xv.x);
                    bp[4*q+1] = tf32b(tkt1*yv.y - tkt*xv.y);
                    bp[4*q+2] = tf32b(tkt1*yv.z - tkt*xv.z);
                    bp[4*q+3] = tf32b(tkt1*yv.w - tkt*xv.w);
                }
            } else {
                #pragma unroll
                for (int q = 0; q < 16; q++) bp[q] = 0u;
            }
        }
        __syncthreads();
        #pragma unroll
        for (int ks = 0; ks < 4; ks++) {
            int kb = ks * 8;
            unsigned a0 = As[(kb+t4  )*72 + m0w + g];
            unsigned a1 = As[(kb+t4  )*72 + m0w + g + 8];
            unsigned a2 = As[(kb+t4+4)*72 + m0w + g];
            unsigned a3 = As[(kb+t4+4)*72 + m0w + g + 8];
            #pragma unroll
            for (int j = 0; j < 8; j++) {
                unsigned b0 = Bs[(kb+t4  )*136 + jb + 8*j + g];
                unsigned b1 = Bs[(kb+t4+4)*136 + jb + 8*j + g];
                asm volatile(
                    "mma.sync.aligned.m16n8k8.row.col.f32.tf32.tf32.f32 "
                    "{%0,%1,%2,%3}, {%4,%5,%6,%7}, {%8,%9}, {%0,%1,%2,%3};"
                    : "+f"(c[j][0]), "+f"(c[j][1]), "+f"(c[j][2]), "+f"(c[j][3])
                    : "r"(a0), "r"(a1), "r"(a2), "r"(a3), "r"(b0), "r"(b1));
            }
        }
    }

    float* dst = g_sig + (size_t)b*SIGDIM + FF;
    #pragma unroll
    for (int j = 0; j < 8; j++) {
        int row = i0 + m0w + g;
        int col = jb + 8*j + 2*t4;
        dst[(size_t)row    *FF + col]     = tf32r(c[j][0]);
        dst[(size_t)row    *FF + col + 1] = tf32r(c[j][1]);
        dst[(size_t)(row+8)*FF + col]     = tf32r(c[j][2]);
        dst[(size_t)(row+8)*FF + col + 1] = tf32r(c[j][3]);
    }
    if (blockIdx.x == 0 && tid < FF) {
        g_sig[(size_t)b*SIGDIM + tid] = tf32r(
            __ldg(&tk[SS-1]) * Xb[(size_t)(SS-1)*FF + tid] - tk0 * Xb[tid]);
    }
}

/* =================================================================
   z1 = sig@w1, zs = sig@ws via tf32 mma (unchanged from R11).
   grid (8 ntiles of 64, 12 ksplit of 1376, 2), 128 threads.
   ================================================================= */
__global__ void __launch_bounds__(128)
k_siggemm(const float* __restrict__ w1, const float* __restrict__ ws)
{
    const float* Bw = blockIdx.z ? ws : w1;
    float* o        = blockIdx.z ? g_zs : g_z1;
    int n0 = blockIdx.x * 64;
    int k0 = blockIdx.y * 1376;

    __shared__ __align__(16) unsigned As[32*72];
    __shared__ __align__(16) unsigned Bs[32*72];

    int tid  = threadIdx.x;
    int lane = tid & 31;
    int warp = tid >> 5;
    int g  = lane >> 2, t4 = lane & 3;
    int m0w = warp * 16;

    float c[8][4];
    #pragma unroll
    for (int j = 0; j < 8; j++)
        { c[j][0]=0.f; c[j][1]=0.f; c[j][2]=0.f; c[j][3]=0.f; }

    const unsigned* A = reinterpret_cast<const unsigned*>(g_sig);
    int am = tid >> 1, akh = (tid & 1) * 16;
    int bk = tid >> 2, bnq = (tid & 3) * 16;

    for (int kk = 0; kk < 1376; kk += 32) {
        int kg = k0 + kk;
        __syncthreads();
        {
            const unsigned* ap = &A[(size_t)am*SIGDIM + kg + akh];
            uint4 u0 = *reinterpret_cast<const uint4*>(ap);
            uint4 u1 = *reinterpret_cast<const uint4*>(ap + 4);
            uint4 u2 = *reinterpret_cast<const uint4*>(ap + 8);
            uint4 u3 = *reinterpret_cast<const uint4*>(ap + 12);
            As[(akh+ 0)*72 + am] = u0.x; As[(akh+ 1)*72 + am] = u0.y;
            As[(akh+ 2)*72 + am] = u0.z; As[(akh+ 3)*72 + am] = u0.w;
            As[(akh+ 4)*72 + am] = u1.x; As[(akh+ 5)*72 + am] = u1.y;
            As[(akh+ 6)*72 + am] = u1.z; As[(akh+ 7)*72 + am] = u1.w;
            As[(akh+ 8)*72 + am] = u2.x; As[(akh+ 9)*72 + am] = u2.y;
            As[(akh+10)*72 + am] = u2.z; As[(akh+11)*72 + am] = u2.w;
            As[(akh+12)*72 + am] = u3.x; As[(akh+13)*72 + am] = u3.y;
            As[(akh+14)*72 + am] = u3.z; As[(akh+15)*72 + am] = u3.w;
        }
        {
            const float* bp = &Bw[(size_t)(kg + bk)*UU + n0 + bnq];
            float4 f0 = *reinterpret_cast<const float4*>(bp);
            float4 f1 = *reinterpret_cast<const float4*>(bp + 4);
            float4 f2 = *reinterpret_cast<const float4*>(bp + 8);
            float4 f3 = *reinterpret_cast<const float4*>(bp + 12);
            uint4 v0 = make_uint4(tf32b(f0.x), tf32b(f0.y), tf32b(f0.z), tf32b(f0.w));
            uint4 v1 = make_uint4(tf32b(f1.x), tf32b(f1.y), tf32b(f1.z), tf32b(f1.w));
            uint4 v2 = make_uint4(tf32b(f2.x), tf32b(f2.y), tf32b(f2.z), tf32b(f2.w));
            uint4 v3 = make_uint4(tf32b(f3.x), tf32b(f3.y), tf32b(f3.z), tf32b(f3.w));
            *reinterpret_cast<uint4*>(&Bs[bk*72 + bnq])      = v0;
            *reinterpret_cast<uint4*>(&Bs[bk*72 + bnq + 4])  = v1;
            *reinterpret_cast<uint4*>(&Bs[bk*72 + bnq + 8])  = v2;
            *reinterpret_cast<uint4*>(&Bs[bk*72 + bnq + 12]) = v3;
        }
        __syncthreads();
        #pragma unroll
        for (int ks = 0; ks < 4; ks++) {
            int kb = ks * 8;
            unsigned a0 = As[(kb+t4  )*72 + m0w + g];
            unsigned a1 = As[(kb+t4  )*72 + m0w + g + 8];
            unsigned a2 = As[(kb+t4+4)*72 + m0w + g];
            unsigned a3 = As[(kb+t4+4)*72 + m0w + g + 8];
            #pragma unroll
            for (int j = 0; j < 8; j++) {
                unsigned b0 = Bs[(kb+t4  )*72 + 8*j + g];
                unsigned b1 = Bs[(kb+t4+4)*72 + 8*j + g];
                asm volatile(
                    "mma.sync.aligned.m16n8k8.row.col.f32.tf32.tf32.f32 "
                    "{%0,%1,%2,%3}, {%4,%5,%6,%7}, {%8,%9}, {%0,%1,%2,%3};"
                    : "+f"(c[j][0]), "+f"(c[j][1]), "+f"(c[j][2]), "+f"(c[j][3])
                    : "r"(a0), "r"(a1), "r"(a2), "r"(a3), "r"(b0), "r"(b1));
            }
        }
    }
    #pragma unroll
    for (int j = 0; j < 8; j++) {
        int row = m0w + g;
        int col = n0 + 8*j + 2*t4;
        atomicAdd(&o[(size_t)row    *UU + col],     c[j][0]);
        atomicAdd(&o[(size_t)row    *UU + col + 1], c[j][1]);
        atomicAdd(&o[(size_t)(row+8)*UU + col],     c[j][2]);
        atomicAdd(&o[(size_t)(row+8)*UU + col + 1], c[j][3]);
    }
}

/* =================================================================
   k_tail: fused h2-GEMV + g3/g4-GEMVs + GLU + LN + softmax -> attn.
   One CTA (512 threads) per 2 batches; grid 32.
   thread = (ks = tid>>7 in 0..3 : K-segment, nq = tid&127 : n-quad).
   ================================================================= */
__global__ void __launch_bounds__(512)
k_tail(const float* __restrict__ b1, const float* __restrict__ w2,
       const float* __restrict__ b2, const float* __restrict__ w3,
       const float* __restrict__ b3, const float* __restrict__ w4,
       const float* __restrict__ b4, const float* __restrict__ bs,
       const float* __restrict__ gamma, const float* __restrict__ beta)
{
    __shared__ float h1sh[2][UU];
    __shared__ float h2sh[2][UU];
    __shared__ __align__(16) float red[4][2][UU];
    __shared__ float rbuf[16][4];
    __shared__ float bc[4];

    int tid = threadIdx.x;
    int b0 = blockIdx.x * 2;
    int w = tid >> 5, l = tid & 31;
    int nq = tid & 127, ks = tid >> 7;
    int n0 = nq * 4;
    int kbase = ks * 128;

    /* phase 0: h1 rows */
    {
        float bb = __ldg(&b1[tid]);
        float v0 = g_z1[(size_t)b0*UU + tid] + bb;
        float v1 = g_z1[(size_t)(b0+1)*UU + tid] + bb;
        h1sh[0][tid] = v0 > 0.f ? v0 : expm1f(v0);
        h1sh[1][tid] = v1 > 0.f ? v1 : expm1f(v1);
    }
    __syncthreads();

    /* phase 1: h2 = h1 @ w2 */
    {
        float a00=0.f,a01=0.f,a02=0.f,a03=0.f;
        float a10=0.f,a11=0.f,a12=0.f,a13=0.f;
        #pragma unroll 4
        for (int kk = 0; kk < 128; kk++) {
            int k = kbase + kk;
            float4 wv = *reinterpret_cast<const float4*>(&w2[(size_t)k*UU + n0]);
            float a0 = h1sh[0][k], a1 = h1sh[1][k];
            a00 += a0*wv.x; a01 += a0*wv.y; a02 += a0*wv.z; a03 += a0*wv.w;
            a10 += a1*wv.x; a11 += a1*wv.y; a12 += a1*wv.z; a13 += a1*wv.w;
        }
        *reinterpret_cast<float4*>(&red[ks][0][n0]) = make_float4(a00,a01,a02,a03);
        *reinterpret_cast<float4*>(&red[ks][1][n0]) = make_float4(a10,a11,a12,a13);
    }
    __syncthreads();
    {
        float bb = __ldg(&b2[tid]);
        h2sh[0][tid] = red[0][0][tid]+red[1][0][tid]+red[2][0][tid]+red[3][0][tid] + bb;
        h2sh[1][tid] = red[0][1][tid]+red[1][1][tid]+red[2][1][tid]+red[3][1][tid] + bb;
    }
    __syncthreads();

    /* phase 2: g3 = h2@w3, g4 = h2@w4 */
    float c300=0.f,c301=0.f,c302=0.f,c303=0.f, c310=0.f,c311=0.f,c312=0.f,c313=0.f;
    float c400=0.f,c401=0.f,c402=0.f,c403=0.f, c410=0.f,c411=0.f,c412=0.f,c413=0.f;
    #pragma unroll 4
    for (int kk = 0; kk < 128; kk++) {
        int k = kbase + kk;
        float4 w3v = *reinterpret_cast<const float4*>(&w3[(size_t)k*UU + n0]);
        float4 w4v = *reinterpret_cast<const float4*>(&w4[(size_t)k*UU + n0]);
        float a0 = h2sh[0][k], a1 = h2sh[1][k];
        c300 += a0*w3v.x; c301 += a0*w3v.y; c302 += a0*w3v.z; c303 += a0*w3v.w;
        c310 += a1*w3v.x; c311 += a1*w3v.y; c312 += a1*w3v.z; c313 += a1*w3v.w;
        c400 += a0*w4v.x; c401 += a0*w4v.y; c402 += a0*w4v.z; c403 += a0*w4v.w;
        c410 += a1*w4v.x; c411 += a1*w4v.y; c412 += a1*w4v.z; c413 += a1*w4v.w;
    }
    *reinterpret_cast<float4*>(&red[ks][0][n0]) = make_float4(c300,c301,c302,c303);
    *reinterpret_cast<float4*>(&red[ks][1][n0]) = make_float4(c310,c311,c312,c313);
    __syncthreads();
    float g3v0 = red[0][0][tid]+red[1][0][tid]+red[2][0][tid]+red[3][0][tid] + __ldg(&b3[tid]);
    float g3v1 = red[0][1][tid]+red[1][1][tid]+red[2][1][tid]+red[3][1][tid] + __ldg(&b3[tid]);
    __syncthreads();
    *reinterpret_cast<float4*>(&red[ks][0][n0]) = make_float4(c400,c401,c402,c403);
    *reinterpret_cast<float4*>(&red[ks][1][n0]) = make_float4(c410,c411,c412,c413);
    __syncthreads();
    float g4v0 = red[0][0][tid]+red[1][0][tid]+red[2][0][tid]+red[3][0][tid] + __ldg(&b4[tid]);
    float g4v1 = red[0][1][tid]+red[1][1][tid]+red[2][1][tid]+red[3][1][tid] + __ldg(&b4[tid]);

    /* phase 3: y, LN, softmax for both rows */
    float bsv = __ldg(&bs[tid]);
    float y0 = g_zs[(size_t)b0*UU + tid]     + bsv + g4v0 / (1.f + __expf(-g3v0));
    float y1 = g_zs[(size_t)(b0+1)*UU + tid] + bsv + g4v1 / (1.f + __expf(-g3v1));

    float s0 = y0, q0 = y0*y0, s1 = y1, q1 = y1*y1;
    #pragma unroll
    for (int o = 16; o; o >>= 1) {
        s0 += __shfl_xor_sync(0xffffffffu, s0, o);
        q0 += __shfl_xor_sync(0xffffffffu, q0, o);
        s1 += __shfl_xor_sync(0xffffffffu, s1, o);
        q1 += __shfl_xor_sync(0xffffffffu, q1, o);
    }
    if (l == 0) { rbuf[w][0]=s0; rbuf[w][1]=q0; rbuf[w][2]=s1; rbuf[w][3]=q1; }
    __syncthreads();
    if (tid < 64) {
        int wi = tid >> 2, e = tid & 3;
        float v = rbuf[wi][e];
        #pragma unroll
        for (int o = 32; o >= 4; o >>= 1) v += __shfl_xor_sync(0xffffffffu, v, o);
        if (wi == 0) bc[e] = v;
    }
    __syncthreads();
    float mu0 = bc[0]*(1.f/UU), var0 = bc[1]*(1.f/UU) - mu0*mu0;
    float mu1 = bc[2]*(1.f/UU), var1 = bc[3]*(1.f/UU) - mu1*mu1;
    float gm = __ldg(&gamma[tid]), bt = __ldg(&beta[tid]);
    float yn0 = (y0 - mu0) * rsqrtf(var0 + 1e-3f) * gm + bt;
    float yn1 = (y1 - mu1) * rsqrtf(var1 + 1e-3f) * gm + bt;

    float m0 = yn0, m1 = yn1;
    #pragma unroll
    for (int o = 16; o; o >>= 1) {
        m0 = fmaxf(m0, __shfl_xor_sync(0xffffffffu, m0, o));
        m1 = fmaxf(m1, __shfl_xor_sync(0xffffffffu, m1, o));
    }
    if (l == 0) { rbuf[w][0]=m0; rbuf[w][1]=m1; }
    __syncthreads();
    if (tid < 32) {
        int wi = tid >> 1, e = tid & 1;
        float v = rbuf[wi][e];
        #pragma unroll
        for (int o = 16; o >= 2; o >>= 1) v = fmaxf(v, __shfl_xor_sync(0xffffffffu, v, o));
        if (wi == 0) bc[e] = v;
    }
    __syncthreads();
    float e0 = __expf(yn0 - bc[0]);
    float e1 = __expf(yn1 - bc[1]);
    float t0 = e0, t1 = e1;
    #pragma unroll
    for (int o = 16; o; o >>= 1) {
        t0 += __shfl_xor_sync(0xffffffffu, t0, o);
        t1 += __shfl_xor_sync(0xffffffffu, t1, o);
    }
    if (l == 0) { rbuf[w][0]=t0; rbuf[w][1]=t1; }
    __syncthreads();
    if (tid < 32) {
        int wi = tid >> 1, e = tid & 1;
        float v = rbuf[wi][e];
        #pragma unroll
        for (int o = 16; o >= 2; o >>= 1) v += __shfl_xor_sync(0xffffffffu, v, o);
        if (wi == 0) bc[e] = v;
    }
    __syncthreads();
    g_attn[(size_t)b0*UU + tid]     = e0 / bc[0];
    g_attn[(size_t)(b0+1)*UU + tid] = e1 / bc[1];
}

/* ---------------- attn-weighted reductions (unchanged) ---------------- */
__global__ void k_reduce(const float* __restrict__ X, const float* __restrict__ tk)
{
    int b  = blockIdx.x;
    int s0 = blockIdx.y * 64;
    int f  = threadIdx.x;
    const float* Xb = X + (size_t)b * SS * FF;
    float accb = 0.f;
    float accs[NBF] = {};
    for (int ss = 0; ss < 64; ss++) {
        int s = s0 + ss;
        float a  = __ldg(&g_attn[b * UU + s]);
        float xv = __ldg(&tk[s]) * __ldg(&Xb[(size_t)s * FF + f]);
        float sg = 1.f / (1.f + __expf(-xv));
        accb += a * (xv * sg);
        float xs = (xv + 2.2f) * 2.5f;
        float mf = floorf(xs);
        int m = (int)mf;
        float u  = xs - mf;
        float um = 1.f - u;
        float wd0 = u*u*u * (1.f/6.f);
        float wd1 = 0.66666667f + um*um*(0.5f*um - 1.f);
        float wd2 = 0.66666667f + u*u*(0.5f*u - 1.f);
        float wd3 = um*um*um * (1.f/6.f);
        #pragma unroll
        for (int k = 0; k < NBF; k++) {
            int d = m - k;
            float wv = (d == 0) ? wd0 : (d == 1) ? wd1 : (d == 2) ? wd2
                     : (d == 3) ? wd3 : 0.f;
            accs[k] += a * wv;
        }
    }
    atomicAdd(&g_Ab[b * FF + f], accb);
    #pragma unroll
    for (int k = 0; k < NBF; k++)
        atomicAdd(&g_As[(size_t)(b * FF + f) * NBF + k], accs[k]);
}

/* ---------------- warp-broadcast FFMA2 GEMM (R6 core, cur/lstm) -------- */
template<int AMODE, int BTRANS>
__device__ __forceinline__ void gemmW(
    const float* __restrict__ A, int lda, const float* __restrict__ aux,
    const float* __restrict__ Bw, int ldb, float* __restrict__ out, int ldo,
    int n0, int k0, int Kchunk)
{
    __shared__ __align__(16) float Adup[KSTEP][132];
    __shared__ __align__(16) float Bsh[KSTEP][132];
    int tid = threadIdx.x;
    int l = tid & 31;
    int nw = (tid >> 5) * 16;
    ull acc[2][8] = {{0,0,0,0,0,0,0,0},{0,0,0,0,0,0,0,0}};

    for (int kk = 0; kk < Kchunk; kk += KSTEP) {
        int kg = k0 + kk;
        __syncthreads();
        {
            int m = tid >> 2, k4 = (tid & 3) * 4;
            float4 av;
            if (AMODE == 3) {
                int k = kg + k4;
                if (k < UU) {
                    av = *reinterpret_cast<const float4*>(&A[(size_t)m*UU + k]);
                    av.x *= (1.f/SS); av.y *= (1.f/SS);
                    av.z *= (1.f/SS); av.w *= (1.f/SS);
                } else {
                    av = *reinterpret_cast<const float4*>(&aux[(size_t)m*UU + k - UU]);
                }
            } else {
                av = *reinterpret_cast<const float4*>(&A[(size_t)m*lda + kg + k4]);
            }
            *reinterpret_cast<float2*>(&Adup[k4+0][2*m]) = make_float2(av.x, av.x);
            *reinterpret_cast<float2*>(&Adup[k4+1][2*m]) = make_float2(av.y, av.y);
            *reinterpret_cast<float2*>(&Adup[k4+2][2*m]) = make_float2(av.z, av.z);
            *reinterpret_cast<float2*>(&Adup[k4+3][2*m]) = make_float2(av.w, av.w);
        }
        if (!BTRANS) {
            int k = tid >> 4, n8 = (tid & 15) * 8;
            const float* bp = &Bw[(size_t)(kg + k)*ldb + n0 + n8];
            float4 b0 = *reinterpret_cast<const float4*>(bp);
            float4 b1 = *reinterpret_cast<const float4*>(bp + 4);
            *reinterpret_cast<float4*>(&Bsh[k][n8])     = b0;
            *reinterpret_cast<float4*>(&Bsh[k][n8 + 4]) = b1;
        } else {
            int n = tid >> 1, kq = (tid & 1) * 8;
            const float* bp = &Bw[(size_t)(n0 + n)*ldb + kg + kq];
            float4 b0 = *reinterpret_cast<const float4*>(bp);
            float4 b1 = *reinterpret_cast<const float4*>(bp + 4);
            Bsh[kq+0][n] = b0.x; Bsh[kq+1][n] = b0.y;
            Bsh[kq+2][n] = b0.z; Bsh[kq+3][n] = b0.w;
            Bsh[kq+4][n] = b1.x; Bsh[kq+5][n] = b1.y;
            Bsh[kq+6][n] = b1.z; Bsh[kq+7][n] = b1.w;
        }
        __syncthreads();
        #pragma unroll
        for (int c = 0; c < KSTEP; c++) {
            ulonglong2 av = *reinterpret_cast<const ulonglong2*>(&Adup[c][4*l]);
            float4 f0 = *reinterpret_cast<const float4*>(&Bsh[c][nw]);
            float4 f1 = *reinterpret_cast<const float4*>(&Bsh[c][nw + 4]);
            float4 f2 = *reinterpret_cast<const float4*>(&Bsh[c][nw + 8]);
            float4 f3 = *reinterpret_cast<const float4*>(&Bsh[c][nw + 12]);
            ull b[8];
            b[0] = pack2(f0.x, f0.y); b[1] = pack2(f0.z, f0.w);
            b[2] = pack2(f1.x, f1.y); b[3] = pack2(f1.z, f1.w);
            b[4] = pack2(f2.x, f2.y); b[5] = pack2(f2.z, f2.w);
            b[6] = pack2(f3.x, f3.y); b[7] = pack2(f3.z, f3.w);
            #pragma unroll
            for (int p = 0; p < 8; p++) {
                acc[0][p] = fma2(av.x, b[p], acc[0][p]);
                acc[1][p] = fma2(av.y, b[p], acc[1][p]);
            }
        }
    }
    #pragma unroll
    for (int p = 0; p < 8; p++) {
        float2 v0 = unpack2(acc[0][p]);
        float2 v1 = unpack2(acc[1][p]);
        int col = n0 + nw + 2*p;
        atomicAdd(&out[(size_t)(2*l)  *ldo + col],     v0.x);
        atomicAdd(&out[(size_t)(2*l)  *ldo + col + 1], v0.y);
        atomicAdd(&out[(size_t)(2*l+1)*ldo + col],     v1.x);
        atomicAdd(&out[(size_t)(2*l+1)*ldo + col + 1], v1.y);
    }
}

/* current*S = Ab@base_w + As . spline_w   grid (4 ntiles, 9 parts) */
__global__ void k_cur(const float* __restrict__ base_w, const float* __restrict__ spline_w)
{
    int n0 = blockIdx.x * 128;
    int part = blockIdx.y;
    if (part == 0)
        gemmW<0,0>(g_Ab, FF, nullptr, base_w, UU, g_cur, UU, n0, 0, FF);
    else
        gemmW<0,1>(g_As, FF * NBF, nullptr, spline_w, FF * NBF, g_cur, UU,
                   n0, (part - 1) * 128, 128);
}

/* 4 gate GEMMs, A = [cur/S | h_prev] built in A-load   grid (4, 4, 8) */
__global__ void k_lstm(const float* __restrict__ h_prev,
                       const float* __restrict__ wf, const float* __restrict__ wi,
                       const float* __restrict__ wc, const float* __restrict__ wo)
{
    const float* w = (blockIdx.y == 0) ? wf : (blockIdx.y == 1) ? wi
                   : (blockIdx.y == 2) ? wc : wo;
    float* o = g_gates + (size_t)blockIdx.y * BU;
    gemmW<3,0>(g_cur, UU, h_prev, w, UU, o, UU,
               blockIdx.x * 128, blockIdx.z * 128, 128);
}

/* gate nonlinearities + state update */
__global__ void k_fin(const float* __restrict__ c_prev,
                      const float* __restrict__ bf, const float* __restrict__ bi,
                      const float* __restrict__ bc, const float* __restrict__ bo,
                      float* __restrict__ out, int out_size)
{
    int i = blockIdx.x * blockDim.x + threadIdx.x;
    int u = i & (UU - 1);
    float fg = 1.f / (1.f + __expf(-(g_gates[i]          + bf[u])));
    float ig = 1.f / (1.f + __expf(-(g_gates[BU + i]     + bi[u])));
    float cd = tanhf(              g_gates[2 * BU + i]   + bc[u]);
    float og = 1.f / (1.f + __expf(-(g_gates[3 * BU + i] + bo[u])));
    float c = fg * c_prev[i] + ig * cd;
    float h = og * tanhf(c);
    out[i] = h;
    if (out_size >= 2 * BU) out[BU + i] = c;
}

/* ------------------------------------------------------------------ */
extern "C" void kernel_launch(void* const* d_in, const int* in_sizes, int n_in,
                              void* d_out, int out_size)
{
    const float* X       = (const float*)d_in[0];
    const float* h_prev  = (const float*)d_in[1];
    const float* c_prev  = (const float*)d_in[2];
    const float* tk      = (const float*)d_in[3];
    const float* base_w  = (const float*)d_in[4];
    const float* spl_w   = (const float*)d_in[5];
    const float* w1      = (const float*)d_in[6];
    const float* b1      = (const float*)d_in[7];
    const float* w2      = (const float*)d_in[8];
    const float* b2      = (const float*)d_in[9];
    const float* w3      = (const float*)d_in[10];
    const float* b3      = (const float*)d_in[11];
    const float* w4      = (const float*)d_in[12];
    const float* b4      = (const float*)d_in[13];
    const float* ws      = (const float*)d_in[14];
    const float* bs      = (const float*)d_in[15];
    const float* gamma   = (const float*)d_in[16];
    const float* beta    = (const float*)d_in[17];
    const float* wf      = (const float*)d_in[18];
    const float* bf      = (const float*)d_in[19];
    const float* wi      = (const float*)d_in[20];
    const float* bi      = (const float*)d_in[21];
    const float* wc      = (const float*)d_in[22];
    const float* bc      = (const float*)d_in[23];
    const float* wo      = (const float*)d_in[24];
    const float* bo      = (const float*)d_in[25];
    float* out = (float*)d_out;

    k_zero   <<<256, 256>>>();
    k_sig    <<<dim3(2, BB), 256>>>(X, tk);
    k_siggemm<<<dim3(8, 12, 2), 128>>>(w1, ws);
    k_tail   <<<32, 512>>>(b1, w2, b2, w3, b3, w4, b4, bs, gamma, beta);
    k_reduce <<<dim3(BB, 8), 128>>>(X, tk);
    k_cur    <<<dim3(4, 9), 256>>>(base_w, spl_w);
    k_lstm   <<<dim3(4, 4, 8), 256>>>(h_prev, wf, wi, wc, wo);
    k_fin    <<<BU / 256, 256>>>(c_prev, bf, bi, bc, bo, out, out_size);
}